// round 13
// baseline (speedup 1.0000x reference)
#include <cuda_runtime.h>
#include <cuda_bf16.h>
#include <cstdint>

// ============================================================================
// HistCausalEncoder: B=16,T=64,P=64,IN=256,ACT=64,OUT=256,H=4
// phase1 (HMMA): u = b + [a-hist|o] @ Wk                 (dense, parallel)
// vpass  (HMMA): out[t0+d] += sum_{j=1..d} C_j u[t0+d-j] (parallel cross terms)
// quad   (HMMA): z_{t0+d}  = acc + sum_h G^{(d)}_h z_{t0-4+h}, d=0..3
//   -> 16 sequential launches of 256 CTAs (4-step unrolled recurrence).
// All GEMMs: 3-term bf16 split Xh*Wh + Xl*Wh + Xh*Wl, fp32 accum, mma.sync.
// ============================================================================

// fp32 chain temps for unrolled-weight prep
__device__ float g_G1f[4][256][256];
__device__ float g_G2f[4][256][256];
__device__ float g_C2f[256][256];

// bf16 split weights: g_U[d][h] = G^{(d)}_h (d=0 -> W_h); g_C[j] = C_{j+1}
__device__ __align__(256) __nv_bfloat16 g_Uh[4][4][256][256];
__device__ __align__(256) __nv_bfloat16 g_Ul[4][4][256][256];
__device__ __align__(256) __nv_bfloat16 g_Ch[3][256][256];
__device__ __align__(256) __nv_bfloat16 g_Cl[3][256][256];
__device__ __align__(256) __nv_bfloat16 g_Kh[256 * 512];     // phase1 W hi [n][k]
__device__ __align__(256) __nv_bfloat16 g_Kl[256 * 512];
__device__ __align__(256) __nv_bfloat16 g_Xh[65536ull * 512];// packed input hi
__device__ __align__(256) __nv_bfloat16 g_Xl[65536ull * 512];
__device__ __align__(256) __nv_bfloat16 g_uh[64][1024][256]; // u all t, hi
__device__ __align__(256) __nv_bfloat16 g_ul[64][1024][256];
__device__ __align__(256) __nv_bfloat16 g_zh[64][1024][256]; // z ring hi
__device__ __align__(256) __nv_bfloat16 g_zl[64][1024][256];

// ---------- helpers ----------
__device__ __forceinline__ uint32_t smem_u32(const void* p) {
    uint32_t a;
    asm("{ .reg .u64 t; cvta.to.shared.u64 t, %1; cvt.u32.u64 %0, t; }" : "=r"(a) : "l"(p));
    return a;
}
__device__ __forceinline__ void cp16(uint32_t dst, const void* src) {
    asm volatile("cp.async.cg.shared.global [%0], [%1], 16;" :: "r"(dst), "l"(src) : "memory");
}
__device__ __forceinline__ void cp_commit() { asm volatile("cp.async.commit_group;" ::: "memory"); }
template <int N> __device__ __forceinline__ void cp_wait() {
    asm volatile("cp.async.wait_group %0;" :: "n"(N) : "memory");
}
__device__ __forceinline__ void ldx4(uint32_t (&r)[4], uint32_t a) {
    asm volatile("ldmatrix.sync.aligned.m8n8.x4.shared.b16 {%0,%1,%2,%3}, [%4];"
                 : "=r"(r[0]), "=r"(r[1]), "=r"(r[2]), "=r"(r[3]) : "r"(a));
}
__device__ __forceinline__ void mma16816(float (&d)[4], const uint32_t (&a)[4],
                                         uint32_t b0, uint32_t b1) {
    asm volatile("mma.sync.aligned.m16n8k16.row.col.f32.bf16.bf16.f32 "
                 "{%0,%1,%2,%3}, {%4,%5,%6,%7}, {%8,%9}, {%0,%1,%2,%3};"
                 : "+f"(d[0]), "+f"(d[1]), "+f"(d[2]), "+f"(d[3])
                 : "r"(a[0]), "r"(a[1]), "r"(a[2]), "r"(a[3]), "r"(b0), "r"(b1));
}
__device__ __forceinline__ void splitbf(float v, __nv_bfloat16& hi, __nv_bfloat16& lo) {
    hi = __float2bfloat16_rn(v);
    lo = __float2bfloat16_rn(v - __bfloat162float(hi));
}

// ---------- prepW: split W (d=0 slots), phase1 Wk, C1=W3 ----------
__global__ void prepW_kernel(const float* __restrict__ W) {
    int idx = blockIdx.x * 256 + threadIdx.x;        // < 262144 + 131072
    if (idx < 4 * 256 * 256) {
        int h = idx >> 16, n = (idx >> 8) & 255, k = idx & 255;
        __nv_bfloat16 hi, lo;
        splitbf(W[n * 1536 + h * 320 + k], hi, lo);
        g_Uh[0][h][n][k] = hi; g_Ul[0][h][n][k] = lo;
        if (h == 3) { g_Ch[0][n][k] = hi; g_Cl[0][n][k] = lo; }   // C1 = W3
    } else {
        int j = idx - 262144;
        int n = j >> 9, k = j & 511;
        int col = (k < 256) ? ((k >> 6) * 320 + 256 + (k & 63)) : (1280 + (k - 256));
        splitbf(W[n * 1536 + col], g_Kh[j], g_Kl[j]);
    }
}

// ---------- prepA: G1_h = [h>0]W_{h-1} + W3@W_h ;  C2 = W2 + W3@W3 ----------
__global__ void prepA_kernel(const float* __restrict__ W) {
    int idx = blockIdx.x * 256 + threadIdx.x;        // < 5*65536
    int job = idx >> 16, n = (idx >> 8) & 255, k = idx & 255;
    const float* w3 = W + n * 1536 + 960;
    float acc;
    if (job < 4) {
        acc = (job > 0) ? W[n * 1536 + (job - 1) * 320 + k] : 0.f;
        for (int m = 0; m < 256; ++m) acc += w3[m] * W[m * 1536 + job * 320 + k];
        g_G1f[job][n][k] = acc;
        splitbf(acc, g_Uh[1][job][n][k], g_Ul[1][job][n][k]);
    } else {
        acc = W[n * 1536 + 640 + k];                 // W2
        for (int m = 0; m < 256; ++m) acc += w3[m] * W[m * 1536 + 960 + k];
        g_C2f[n][k] = acc;
        splitbf(acc, g_Ch[1][n][k], g_Cl[1][n][k]);
    }
}

// ---------- prepB: G2_h = [h>1]W_{h-2} + W3@G1_h + W2@W_h ; C3 = W1+W2@W3+W3@C2
__global__ void prepB_kernel(const float* __restrict__ W) {
    int idx = blockIdx.x * 256 + threadIdx.x;        // < 5*65536
    int job = idx >> 16, n = (idx >> 8) & 255, k = idx & 255;
    const float* w3 = W + n * 1536 + 960;
    const float* w2 = W + n * 1536 + 640;
    float acc;
    if (job < 4) {
        acc = (job > 1) ? W[n * 1536 + (job - 2) * 320 + k] : 0.f;
        for (int m = 0; m < 256; ++m) acc += w3[m] * g_G1f[job][m][k];
        for (int m = 0; m < 256; ++m) acc += w2[m] * W[m * 1536 + job * 320 + k];
        g_G2f[job][n][k] = acc;
        splitbf(acc, g_Uh[2][job][n][k], g_Ul[2][job][n][k]);
    } else {
        acc = W[n * 1536 + 320 + k];                 // W1
        for (int m = 0; m < 256; ++m) acc += w2[m] * W[m * 1536 + 960 + k];
        for (int m = 0; m < 256; ++m) acc += w3[m] * g_C2f[m][k];
        splitbf(acc, g_Ch[2][n][k], g_Cl[2][n][k]);
    }
}

// ---------- prepC: G3_h = [h>2]W_{h-3} + W3@G2_h + W2@G1_h + W1@W_h ----------
__global__ void prepC_kernel(const float* __restrict__ W) {
    int idx = blockIdx.x * 256 + threadIdx.x;        // < 4*65536
    int h = idx >> 16, n = (idx >> 8) & 255, k = idx & 255;
    const float* w3 = W + n * 1536 + 960;
    const float* w2 = W + n * 1536 + 640;
    const float* w1 = W + n * 1536 + 320;
    float acc = (h > 2) ? W[n * 1536 + (h - 3) * 320 + k] : 0.f;
    for (int m = 0; m < 256; ++m) acc += w3[m] * g_G2f[h][m][k];
    for (int m = 0; m < 256; ++m) acc += w2[m] * g_G1f[h][m][k];
    for (int m = 0; m < 256; ++m) acc += w1[m] * W[m * 1536 + h * 320 + k];
    splitbf(acc, g_Uh[3][h][n][k], g_Ul[3][h][n][k]);
}

// ---------- prepX: pack [a_{t-4..t-1} | o_t] as bf16 hi/lo (float4 loads) ----
__global__ void prepX_kernel(const float* __restrict__ o, const float* __restrict__ act) {
    unsigned idx = blockIdx.x * 256 + threadIdx.x;   // < 65536*128 (4 k each)
    int row = idx >> 7, k = (idx & 127) * 4;
    int b = row >> 12, t = (row >> 6) & 63, p = row & 63;
    float4 v;
    if (k < 256) {
        int h = k >> 6, ts = t - 4 + h;
        v = (ts >= 0)
          ? *reinterpret_cast<const float4*>(&act[((b * 64 + ts) * 64 + p) * 64 + (k & 63)])
          : make_float4(0.f, 0.f, 0.f, 0.f);
    } else {
        v = *reinterpret_cast<const float4*>(&o[(size_t)row * 256 + (k - 256)]);
    }
    __nv_bfloat16 h0, l0, h1, l1, h2, l2, h3, l3;
    splitbf(v.x, h0, l0); splitbf(v.y, h1, l1);
    splitbf(v.z, h2, l2); splitbf(v.w, h3, l3);
    const size_t base = (size_t)row * 512 + k;
    *reinterpret_cast<__nv_bfloat162*>(&g_Xh[base])     = __nv_bfloat162(h0, h1);
    *reinterpret_cast<__nv_bfloat162*>(&g_Xh[base + 2]) = __nv_bfloat162(h2, h3);
    *reinterpret_cast<__nv_bfloat162*>(&g_Xl[base])     = __nv_bfloat162(l0, l1);
    *reinterpret_cast<__nv_bfloat162*>(&g_Xl[base + 2]) = __nv_bfloat162(l2, l3);
}

// ============================================================================
// phase 1: dense HMMA GEMM  out[65536,256] = X @ Wk^T + bias
// CTA 128x128, 256 thr, 3-stage. Epilogue: ring seed t=0, split-u for all t>=1.
// ============================================================================
#define P1_STRIDE 144
#define P1_AMAT   18432
#define P1_BUF    73728
#define P1_STAGES 3

__global__ void __launch_bounds__(256) phase1_mma(
    const float* __restrict__ bias, float* __restrict__ out)
{
    extern __shared__ __align__(16) char sm1[];
    const uint32_t sb = smem_u32(sm1);
    const int tid = threadIdx.x, warp = tid >> 5, lane = tid & 31;
    const int Nbase = blockIdx.x * 128;
    const int Mbase = blockIdx.y * 128;
    const int wm = warp >> 1, wn = warp & 1;

    float acc[2][8][4];
    #pragma unroll
    for (int mi = 0; mi < 2; ++mi)
        #pragma unroll
        for (int ni = 0; ni < 8; ++ni)
            #pragma unroll
            for (int q = 0; q < 4; ++q) acc[mi][ni][q] = 0.f;

    auto load = [&](int c, int st) {
        const int k0 = c * 64;
        const uint32_t ab = sb + st * P1_BUF;
        const char* xh = (const char*)g_Xh + (size_t)Mbase * 1024 + k0 * 2;
        const char* xl = (const char*)g_Xl + (size_t)Mbase * 1024 + k0 * 2;
        const char* kh = (const char*)g_Kh + (size_t)Nbase * 1024 + k0 * 2;
        const char* kl = (const char*)g_Kl + (size_t)Nbase * 1024 + k0 * 2;
        #pragma unroll
        for (int i = 0; i < 4; ++i) {
            const int id = i * 256 + tid;
            const int row = id >> 3, cq = (id & 7) * 16;
            const uint32_t d = ab + row * P1_STRIDE + cq;
            const size_t g = (size_t)row * 1024 + cq;
            cp16(d,                xh + g);
            cp16(d + P1_AMAT,      xl + g);
            cp16(d + 2 * P1_AMAT,  kh + g);
            cp16(d + 3 * P1_AMAT,  kl + g);
        }
        cp_commit();
    };

    const uint32_t rsel = (uint32_t)((lane & 15) * P1_STRIDE + (lane >> 4) * 16);

    load(0, 0); load(1, 1);
    for (int c = 0; c < 8; ++c) {
        cp_wait<1>();
        __syncthreads();
        const int st = c % 3;
        const uint32_t ab  = sb + st * P1_BUF;
        const uint32_t aA0 = ab + (wm * 32) * P1_STRIDE + rsel;
        const uint32_t aB0 = ab + 2 * P1_AMAT + (wn * 64) * P1_STRIDE + rsel;
        #pragma unroll
        for (int s = 0; s < 4; ++s) {
            const uint32_t off = s * 32;
            uint32_t ah[2][4], al[2][4], bh[4][4], bl[4][4];
            ldx4(ah[0], aA0 + off);
            ldx4(ah[1], aA0 + 16 * P1_STRIDE + off);
            ldx4(al[0], aA0 + P1_AMAT + off);
            ldx4(al[1], aA0 + P1_AMAT + 16 * P1_STRIDE + off);
            #pragma unroll
            for (int j = 0; j < 4; ++j) {
                ldx4(bh[j], aB0 + j * 16 * P1_STRIDE + off);
                ldx4(bl[j], aB0 + P1_AMAT + j * 16 * P1_STRIDE + off);
            }
            #pragma unroll
            for (int mi = 0; mi < 2; ++mi)
                #pragma unroll
                for (int ni = 0; ni < 8; ++ni) {
                    const int nb = ni >> 1, sel = ni & 1;
                    const uint32_t B0h = bh[nb][sel], B1h = bh[nb][sel + 2];
                    const uint32_t B0l = bl[nb][sel], B1l = bl[nb][sel + 2];
                    mma16816(acc[mi][ni], ah[mi], B0h, B1h);
                    mma16816(acc[mi][ni], al[mi], B0h, B1h);
                    mma16816(acc[mi][ni], ah[mi], B0l, B1l);
                }
        }
        __syncthreads();
        if (c + 2 < 8) load(c + 2, (c + 2) % 3);
    }

    const int r0 = Mbase + wm * 32 + (lane >> 2);
    const int cb = Nbase + wn * 64 + (lane & 3) * 2;
    #pragma unroll
    for (int mi = 0; mi < 2; ++mi)
        #pragma unroll
        for (int ni = 0; ni < 8; ++ni)
            #pragma unroll
            for (int half = 0; half < 2; ++half) {
                const int r = r0 + mi * 16 + half * 8;
                const int cc = cb + ni * 8;
                const float2 bv = *reinterpret_cast<const float2*>(&bias[cc]);
                const float v0 = acc[mi][ni][half * 2] + bv.x;
                const float v1 = acc[mi][ni][half * 2 + 1] + bv.y;
                *reinterpret_cast<float2*>(&out[(size_t)r * 256 + cc]) = make_float2(v0, v1);
                const int t = (r >> 6) & 63;
                const int rowg = (r >> 12) * 64 + (r & 63);
                __nv_bfloat16 h0, l0, h1, l1;
                splitbf(v0, h0, l0); splitbf(v1, h1, l1);
                if (t == 0) {
                    *reinterpret_cast<__nv_bfloat162*>(&g_zh[0][rowg][cc]) = __nv_bfloat162(h0, h1);
                    *reinterpret_cast<__nv_bfloat162*>(&g_zl[0][rowg][cc]) = __nv_bfloat162(l0, l1);
                } else {
                    *reinterpret_cast<__nv_bfloat162*>(&g_uh[t][rowg][cc]) = __nv_bfloat162(h0, h1);
                    *reinterpret_cast<__nv_bfloat162*>(&g_ul[t][rowg][cc]) = __nv_bfloat162(l0, l1);
                }
            }
}

// ============================================================================
// 64x64-tile kernels (vpass / quad) share geometry
// ============================================================================
#define P2_STRIDE 144
#define P2_MAT    9216
#define P2_BUF    36864
#define P2_STAGES 4

// ---- vpass: out[t0+d] += sum_{j=1..d} C_j @ u[t0+d-j], blocks t0=4bi+1 ----
__global__ void __launch_bounds__(256) vpass_mma(float* __restrict__ out)
{
    extern __shared__ __align__(16) char smv[];
    const uint32_t sb = smem_u32(smv);
    const int tid = threadIdx.x, warp = tid >> 5, lane = tid & 31;
    const int Nbase = blockIdx.x * 64;
    const int Mbase = blockIdx.y * 64;
    const int bi = blockIdx.z / 3, d = blockIdx.z % 3 + 1;
    const int t0 = 4 * bi + 1, tp = t0 + d;
    if (tp > 63) return;
    const int wm = warp >> 1, wn = warp & 1;
    const int NC = 4 * d;

    float acc[4][4];
    #pragma unroll
    for (int ni = 0; ni < 4; ++ni)
        #pragma unroll
        for (int q = 0; q < 4; ++q) acc[ni][q] = 0.f;

    auto load = [&](int c, int st) {
        const int j = (c >> 2) + 1, k0 = (c & 3) * 64;   // term C_j, u[tp-j]
        const uint32_t ab = sb + st * P2_BUF;
        const char* sAh = (const char*)&g_uh[tp - j][Mbase][k0];
        const char* sAl = (const char*)&g_ul[tp - j][Mbase][k0];
        const char* sBh = (const char*)&g_Ch[j - 1][Nbase][k0];
        const char* sBl = (const char*)&g_Cl[j - 1][Nbase][k0];
        #pragma unroll
        for (int i = 0; i < 2; ++i) {
            const int id = i * 256 + tid;
            const int row = id >> 3, cq = (id & 7) * 16;
            const uint32_t dd = ab + row * P2_STRIDE + cq;
            const int g = row * 512 + cq;
            cp16(dd,              sAh + g);
            cp16(dd + P2_MAT,     sAl + g);
            cp16(dd + 2 * P2_MAT, sBh + g);
            cp16(dd + 3 * P2_MAT, sBl + g);
        }
        cp_commit();
    };

    const uint32_t rsel = (uint32_t)((lane & 15) * P2_STRIDE + (lane >> 4) * 16);

    load(0, 0); load(1, 1); load(2, 2);
    for (int c = 0; c < NC; ++c) {
        cp_wait<2>();
        __syncthreads();
        const uint32_t ab  = sb + (c & 3) * P2_BUF;
        const uint32_t aA0 = ab + (wm * 16) * P2_STRIDE + rsel;
        const uint32_t aB0 = ab + 2 * P2_MAT + (wn * 32) * P2_STRIDE + rsel;
        #pragma unroll
        for (int s = 0; s < 4; ++s) {
            const uint32_t off = s * 32;
            uint32_t ah[4], al[4], bh[2][4], bl[2][4];
            ldx4(ah, aA0 + off);
            ldx4(al, aA0 + P2_MAT + off);
            ldx4(bh[0], aB0 + off);
            ldx4(bh[1], aB0 + 16 * P2_STRIDE + off);
            ldx4(bl[0], aB0 + P2_MAT + off);
            ldx4(bl[1], aB0 + P2_MAT + 16 * P2_STRIDE + off);
            #pragma unroll
            for (int ni = 0; ni < 4; ++ni) {
                const int nb = ni >> 1, sel = ni & 1;
                mma16816(acc[ni], ah, bh[nb][sel], bh[nb][sel + 2]);
                mma16816(acc[ni], al, bh[nb][sel], bh[nb][sel + 2]);
                mma16816(acc[ni], ah, bl[nb][sel], bl[nb][sel + 2]);
            }
        }
        __syncthreads();
        if (c + 3 < NC) load(c + 3, (c + 3) & 3);
    }

    const int r0 = Mbase + wm * 16 + (lane >> 2);
    const int cb = Nbase + wn * 32 + (lane & 3) * 2;
    #pragma unroll
    for (int ni = 0; ni < 4; ++ni)
        #pragma unroll
        for (int half = 0; half < 2; ++half) {
            const int r = r0 + half * 8;
            const int cc = cb + ni * 8;
            const int b_ = r >> 6, p_ = r & 63;
            float* op = &out[((b_ * 64 + tp) * 64 + p_) * 256 + cc];
            float2 cur = *reinterpret_cast<float2*>(op);
            cur.x += acc[ni][half * 2];
            cur.y += acc[ni][half * 2 + 1];
            *reinterpret_cast<float2*>(op) = cur;
        }
}

// ---- quad (sequential): d-group computes z_{t0+d} from z_{t0-4..t0-1} ----
__global__ void __launch_bounds__(256) quad_mma(float* __restrict__ out, const int t0)
{
    extern __shared__ __align__(16) char sm2[];
    const uint32_t sb = smem_u32(sm2);
    const int tid = threadIdx.x, warp = tid >> 5, lane = tid & 31;
    const int Nbase = blockIdx.x * 64;
    const int d = blockIdx.y >> 4;
    const int Mbase = (blockIdx.y & 15) * 64;
    const int tOut = t0 + d;
    if (tOut > 63) return;
    const __nv_bfloat16 (*Wh)[256][256] = g_Uh[d];
    const __nv_bfloat16 (*Wl)[256][256] = g_Ul[d];
    const int wm = warp >> 1, wn = warp & 1;

    const int h0 = (t0 >= 4) ? 0 : 4 - t0;
    const int NC = 4 * (4 - h0);

    float acc[4][4];
    #pragma unroll
    for (int ni = 0; ni < 4; ++ni)
        #pragma unroll
        for (int q = 0; q < 4; ++q) acc[ni][q] = 0.f;

    auto load = [&](int c, int st) {
        const int kc = h0 * 4 + c;
        const int h = kc >> 2, ts = t0 - 4 + h, k0 = (kc & 3) * 64;
        const uint32_t ab = sb + st * P2_BUF;
        const char* sAh = (const char*)&g_zh[ts][Mbase][k0];
        const char* sAl = (const char*)&g_zl[ts][Mbase][k0];
        const char* sBh = (const char*)&Wh[h][Nbase][k0];
        const char* sBl = (const char*)&Wl[h][Nbase][k0];
        #pragma unroll
        for (int i = 0; i < 2; ++i) {
            const int id = i * 256 + tid;
            const int row = id >> 3, cq = (id & 7) * 16;
            const uint32_t dd = ab + row * P2_STRIDE + cq;
            const int g = row * 512 + cq;
            cp16(dd,              sAh + g);
            cp16(dd + P2_MAT,     sAl + g);
            cp16(dd + 2 * P2_MAT, sBh + g);
            cp16(dd + 3 * P2_MAT, sBl + g);
        }
        cp_commit();
    };

    const uint32_t rsel = (uint32_t)((lane & 15) * P2_STRIDE + (lane >> 4) * 16);

    load(0, 0); load(1, 1); load(2, 2);
    for (int c = 0; c < NC; ++c) {
        cp_wait<2>();
        __syncthreads();
        const int st = c & 3;
        const uint32_t ab  = sb + st * P2_BUF;
        const uint32_t aA0 = ab + (wm * 16) * P2_STRIDE + rsel;
        const uint32_t aB0 = ab + 2 * P2_MAT + (wn * 32) * P2_STRIDE + rsel;
        #pragma unroll
        for (int s = 0; s < 4; ++s) {
            const uint32_t off = s * 32;
            uint32_t ah[4], al[4], bh[2][4], bl[2][4];
            ldx4(ah, aA0 + off);
            ldx4(al, aA0 + P2_MAT + off);
            ldx4(bh[0], aB0 + off);
            ldx4(bh[1], aB0 + 16 * P2_STRIDE + off);
            ldx4(bl[0], aB0 + P2_MAT + off);
            ldx4(bl[1], aB0 + P2_MAT + 16 * P2_STRIDE + off);
            #pragma unroll
            for (int ni = 0; ni < 4; ++ni) {
                const int nb = ni >> 1, sel = ni & 1;
                mma16816(acc[ni], ah, bh[nb][sel], bh[nb][sel + 2]);
                mma16816(acc[ni], al, bh[nb][sel], bh[nb][sel + 2]);
                mma16816(acc[ni], ah, bl[nb][sel], bl[nb][sel + 2]);
            }
        }
        __syncthreads();
        if (c + 3 < NC) load(c + 3, (c + 3) & 3);
    }

    // epilogue: out RMW (u + cross already there) + bf16 ring write
    const int r0 = Mbase + wm * 16 + (lane >> 2);
    const int cb = Nbase + wn * 32 + (lane & 3) * 2;
    #pragma unroll
    for (int ni = 0; ni < 4; ++ni)
        #pragma unroll
        for (int half = 0; half < 2; ++half) {
            const int r = r0 + half * 8;
            const int cc = cb + ni * 8;
            const int b_ = r >> 6, p_ = r & 63;
            float* op = &out[((b_ * 64 + tOut) * 64 + p_) * 256 + cc];
            float2 cur = *reinterpret_cast<float2*>(op);
            const float v0 = cur.x + acc[ni][half * 2];
            const float v1 = cur.y + acc[ni][half * 2 + 1];
            *reinterpret_cast<float2*>(op) = make_float2(v0, v1);
            __nv_bfloat16 h0, l0, h1, l1;
            splitbf(v0, h0, l0); splitbf(v1, h1, l1);
            *reinterpret_cast<__nv_bfloat162*>(&g_zh[tOut][r][cc]) = __nv_bfloat162(h0, h1);
            *reinterpret_cast<__nv_bfloat162*>(&g_zl[tOut][r][cc]) = __nv_bfloat162(l0, l1);
        }
}

// ---------- launch ----------
extern "C" void kernel_launch(void* const* d_in, const int* in_sizes, int n_in,
                              void* d_out, int out_size)
{
    const float* o_in = (const float*)d_in[0];   // (16,64,64,256)
    const float* a_in = (const float*)d_in[1];   // (16,64,64,64)
    const float* W_in = (const float*)d_in[2];   // (256,1536)
    const float* b_in = (const float*)d_in[3];   // (256,)
    float* out = (float*)d_out;                  // (16,64,64,256)

    cudaFuncSetAttribute(phase1_mma, cudaFuncAttributeMaxDynamicSharedMemorySize,
                         P1_STAGES * P1_BUF);
    cudaFuncSetAttribute(vpass_mma, cudaFuncAttributeMaxDynamicSharedMemorySize,
                         P2_STAGES * P2_BUF);
    cudaFuncSetAttribute(quad_mma, cudaFuncAttributeMaxDynamicSharedMemorySize,
                         P2_STAGES * P2_BUF);

    prepW_kernel<<<1536, 256>>>(W_in);
    prepX_kernel<<<32768, 256>>>(o_in, a_in);
    prepA_kernel<<<1280, 256>>>(W_in);
    prepB_kernel<<<1280, 256>>>(W_in);
    prepC_kernel<<<1024, 256>>>(W_in);
    phase1_mma<<<dim3(2, 512), 256, P1_STAGES * P1_BUF>>>(b_in, out);
    vpass_mma<<<dim3(4, 16, 48), 256, P2_STAGES * P2_BUF>>>(out);
    for (int bi = 0; bi < 16; ++bi)              // 16 sequential 4-step blocks
        quad_mma<<<dim3(4, 64), 256, P2_STAGES * P2_BUF>>>(out, 1 + 4 * bi);
}

// round 14
// speedup vs baseline: 1.3177x; 1.3177x over previous
#include <cuda_runtime.h>
#include <cuda_bf16.h>
#include <cstdint>

// ============================================================================
// HistCausalEncoder: B=16,T=64,P=64,IN=256,ACT=64,OUT=256,H=4
// phase1 (HMMA): u = b + [a-hist|o] @ Wk                 (dense, parallel)
// prepG  (HMMA): 4-step unrolled weights G^{(d)}_h, C_j  (3 chained launches)
// vpass  (HMMA): out[t0+d] += sum_{j=1..d} C_j u[t0+d-j] (parallel cross terms)
// quad   (HMMA): z_{t0+d}  = acc + sum_h G^{(d)}_h z_{t0-4+h}, d=0..3
//   -> 16 sequential launches of 256 CTAs (4-step unrolled recurrence).
// All GEMMs: 3-term bf16 split Xh*Wh + Xl*Wh + Xh*Wl, fp32 accum, mma.sync.
// R14 vs R13: naive O(256)-loop prep (210us) -> HMMA prepG (~25us);
// phase1 128x64 tiles 2-stage (2 CTA/SM); quad/vpass 2-stage (2 CTA/SM).
// ============================================================================

// bf16 split weights: g_U[d][h] = G^{(d)}_h (d=0 -> W_h); g_C[j] = C_{j+1}
__device__ __align__(256) __nv_bfloat16 g_Uh[4][4][256][256];
__device__ __align__(256) __nv_bfloat16 g_Ul[4][4][256][256];
__device__ __align__(256) __nv_bfloat16 g_Ch[3][256][256];
__device__ __align__(256) __nv_bfloat16 g_Cl[3][256][256];
// transposed split copies for chain-GEMM B operands:
// slots 0-3: W_h^T, 4-7: G1_h^T, 8: C2^T, 9-12: G2_h^T
__device__ __align__(256) __nv_bfloat16 g_Th[13][256][256];
__device__ __align__(256) __nv_bfloat16 g_Tl[13][256][256];
__device__ __align__(256) __nv_bfloat16 g_Kh[256 * 512];     // phase1 W hi [n][k]
__device__ __align__(256) __nv_bfloat16 g_Kl[256 * 512];
__device__ __align__(256) __nv_bfloat16 g_Xh[65536ull * 512];// packed input hi
__device__ __align__(256) __nv_bfloat16 g_Xl[65536ull * 512];
__device__ __align__(256) __nv_bfloat16 g_uh[64][1024][256]; // u all t, hi
__device__ __align__(256) __nv_bfloat16 g_ul[64][1024][256];
__device__ __align__(256) __nv_bfloat16 g_zh[64][1024][256]; // z ring hi
__device__ __align__(256) __nv_bfloat16 g_zl[64][1024][256];

// ---------- helpers ----------
__device__ __forceinline__ uint32_t smem_u32(const void* p) {
    uint32_t a;
    asm("{ .reg .u64 t; cvta.to.shared.u64 t, %1; cvt.u32.u64 %0, t; }" : "=r"(a) : "l"(p));
    return a;
}
__device__ __forceinline__ void cp16(uint32_t dst, const void* src) {
    asm volatile("cp.async.cg.shared.global [%0], [%1], 16;" :: "r"(dst), "l"(src) : "memory");
}
__device__ __forceinline__ void cp_commit() { asm volatile("cp.async.commit_group;" ::: "memory"); }
template <int N> __device__ __forceinline__ void cp_wait() {
    asm volatile("cp.async.wait_group %0;" :: "n"(N) : "memory");
}
__device__ __forceinline__ void ldx4(uint32_t (&r)[4], uint32_t a) {
    asm volatile("ldmatrix.sync.aligned.m8n8.x4.shared.b16 {%0,%1,%2,%3}, [%4];"
                 : "=r"(r[0]), "=r"(r[1]), "=r"(r[2]), "=r"(r[3]) : "r"(a));
}
__device__ __forceinline__ void mma16816(float (&d)[4], const uint32_t (&a)[4],
                                         uint32_t b0, uint32_t b1) {
    asm volatile("mma.sync.aligned.m16n8k16.row.col.f32.bf16.bf16.f32 "
                 "{%0,%1,%2,%3}, {%4,%5,%6,%7}, {%8,%9}, {%0,%1,%2,%3};"
                 : "+f"(d[0]), "+f"(d[1]), "+f"(d[2]), "+f"(d[3])
                 : "r"(a[0]), "r"(a[1]), "r"(a[2]), "r"(a[3]), "r"(b0), "r"(b1));
}
__device__ __forceinline__ void splitbf(float v, __nv_bfloat16& hi, __nv_bfloat16& lo) {
    hi = __float2bfloat16_rn(v);
    lo = __float2bfloat16_rn(v - __bfloat162float(hi));
}

// ---------- prepW: split W_h (+transposed), phase1 Wk, C1=W3 ----------
__global__ void prepW_kernel(const float* __restrict__ W) {
    int idx = blockIdx.x * 256 + threadIdx.x;        // < 262144 + 131072
    if (idx < 4 * 256 * 256) {
        int h = idx >> 16, n = (idx >> 8) & 255, k = idx & 255;
        __nv_bfloat16 hi, lo;
        splitbf(W[n * 1536 + h * 320 + k], hi, lo);
        g_Uh[0][h][n][k] = hi; g_Ul[0][h][n][k] = lo;
        g_Th[h][k][n] = hi;    g_Tl[h][k][n] = lo;   // W_h^T for chain GEMMs
        if (h == 3) { g_Ch[0][n][k] = hi; g_Cl[0][n][k] = lo; }   // C1 = W3
    } else {
        int j = idx - 262144;
        int n = j >> 9, k = j & 511;
        int col = (k < 256) ? ((k >> 6) * 320 + 256 + (k & 63)) : (1280 + (k - 256));
        splitbf(W[n * 1536 + col], g_Kh[j], g_Kl[j]);
    }
}

// ---------- prepX: pack [a_{t-4..t-1} | o_t] as bf16 hi/lo (float4 loads) ----
__global__ void prepX_kernel(const float* __restrict__ o, const float* __restrict__ act) {
    unsigned idx = blockIdx.x * 256 + threadIdx.x;   // < 65536*128 (4 k each)
    int row = idx >> 7, k = (idx & 127) * 4;
    int b = row >> 12, t = (row >> 6) & 63, p = row & 63;
    float4 v;
    if (k < 256) {
        int h = k >> 6, ts = t - 4 + h;
        v = (ts >= 0)
          ? *reinterpret_cast<const float4*>(&act[((b * 64 + ts) * 64 + p) * 64 + (k & 63)])
          : make_float4(0.f, 0.f, 0.f, 0.f);
    } else {
        v = *reinterpret_cast<const float4*>(&o[(size_t)row * 256 + (k - 256)]);
    }
    __nv_bfloat16 h0, l0, h1, l1, h2, l2, h3, l3;
    splitbf(v.x, h0, l0); splitbf(v.y, h1, l1);
    splitbf(v.z, h2, l2); splitbf(v.w, h3, l3);
    const size_t base = (size_t)row * 512 + k;
    *reinterpret_cast<__nv_bfloat162*>(&g_Xh[base])     = __nv_bfloat162(h0, h1);
    *reinterpret_cast<__nv_bfloat162*>(&g_Xh[base + 2]) = __nv_bfloat162(h2, h3);
    *reinterpret_cast<__nv_bfloat162*>(&g_Xl[base])     = __nv_bfloat162(l0, l1);
    *reinterpret_cast<__nv_bfloat162*>(&g_Xl[base + 2]) = __nv_bfloat162(l2, l3);
}

// ============================================================================
// 64x64-tile geometry shared by prepG / vpass / quad (2-stage pipelines)
// ============================================================================
#define P2_STRIDE 144
#define P2_MAT    9216
#define P2_BUF    36864          // Ah|Al|Bh|Bl per stage

// ---------- prepG_mma: chain GEMMs on tensor pipe ----------
// stage 0: G1_h = [h>0]W_{h-1} + W3@W_h        (jobs 0-3);  C2 = W2 + W3@W3 (job 4)
// stage 1: G2_h = [h>1]W_{h-2} + W3@G1 + W2@W_h (0-3); C3 = W1 + W2@W3 + W3@C2 (4)
// stage 2: G3_h = [h>2]W_{h-3} + W3@G2 + W2@G1 + W1@W_h (0-3)
__device__ __forceinline__ void prep_term(int stage, int job, int term, int& a, int& b) {
    if (stage == 0)      { a = 3; b = (job < 4) ? job : 3; }
    else if (stage == 1) {
        if (job < 4) { if (term == 0) { a = 3; b = 4 + job; } else { a = 2; b = job; } }
        else         { if (term == 0) { a = 2; b = 3; }       else { a = 3; b = 8; } }
    } else {
        if (term == 0)      { a = 3; b = 9 + job; }
        else if (term == 1) { a = 2; b = 4 + job; }
        else                { a = 1; b = job; }
    }
}

__global__ void __launch_bounds__(256) prepG_mma(const float* __restrict__ W, const int stage)
{
    extern __shared__ __align__(16) char smg[];
    const uint32_t sb = smem_u32(smg);
    const int tid = threadIdx.x, warp = tid >> 5, lane = tid & 31;
    const int Nbase = blockIdx.x * 64;               // output col (k) tile
    const int Mbase = blockIdx.y * 64;               // output row (n) tile
    const int job = blockIdx.z;
    const int nterms = (stage == 0) ? 1 : (stage == 1 ? 2 : 3);
    const int NC = 4 * nterms;
    const int wm = warp >> 1, wn = warp & 1;

    float acc[4][4];
    #pragma unroll
    for (int ni = 0; ni < 4; ++ni)
        #pragma unroll
        for (int q = 0; q < 4; ++q) acc[ni][q] = 0.f;

    auto load = [&](int c, int st) {
        const int term = c >> 2, k0 = (c & 3) * 64;
        int a, b; prep_term(stage, job, term, a, b);
        const uint32_t ab = sb + st * P2_BUF;
        const char* sAh = (const char*)&g_Uh[0][a][Mbase][k0];
        const char* sAl = (const char*)&g_Ul[0][a][Mbase][k0];
        const char* sBh = (const char*)&g_Th[b][Nbase][k0];
        const char* sBl = (const char*)&g_Tl[b][Nbase][k0];
        #pragma unroll
        for (int i = 0; i < 2; ++i) {
            const int id = i * 256 + tid;
            const int row = id >> 3, cq = (id & 7) * 16;
            const uint32_t dd = ab + row * P2_STRIDE + cq;
            const int g = row * 512 + cq;
            cp16(dd,              sAh + g);
            cp16(dd + P2_MAT,     sAl + g);
            cp16(dd + 2 * P2_MAT, sBh + g);
            cp16(dd + 3 * P2_MAT, sBl + g);
        }
        cp_commit();
    };

    const uint32_t rsel = (uint32_t)((lane & 15) * P2_STRIDE + (lane >> 4) * 16);

    load(0, 0); load(1, 1);
    for (int c = 0; c < NC; ++c) {
        if (c + 1 < NC) cp_wait<1>(); else cp_wait<0>();
        __syncthreads();
        const uint32_t ab  = sb + (c & 1) * P2_BUF;
        const uint32_t aA0 = ab + (wm * 16) * P2_STRIDE + rsel;
        const uint32_t aB0 = ab + 2 * P2_MAT + (wn * 32) * P2_STRIDE + rsel;
        #pragma unroll
        for (int s = 0; s < 4; ++s) {
            const uint32_t off = s * 32;
            uint32_t ah[4], al[4], bh[2][4], bl[2][4];
            ldx4(ah, aA0 + off);
            ldx4(al, aA0 + P2_MAT + off);
            ldx4(bh[0], aB0 + off);
            ldx4(bh[1], aB0 + 16 * P2_STRIDE + off);
            ldx4(bl[0], aB0 + P2_MAT + off);
            ldx4(bl[1], aB0 + P2_MAT + 16 * P2_STRIDE + off);
            #pragma unroll
            for (int ni = 0; ni < 4; ++ni) {
                const int nb = ni >> 1, sel = ni & 1;
                mma16816(acc[ni], ah, bh[nb][sel], bh[nb][sel + 2]);
                mma16816(acc[ni], al, bh[nb][sel], bh[nb][sel + 2]);
                mma16816(acc[ni], ah, bl[nb][sel], bl[nb][sel + 2]);
            }
        }
        __syncthreads();
        if (c + 2 < NC) load(c + 2, c & 1);
    }

    // shift column in original W (fp32 addend), -1 = none
    int shiftCol = -1;
    if (stage == 0)      { if (job >= 1 && job < 4) shiftCol = (job - 1) * 320;
                           else if (job == 4) shiftCol = 640; }
    else if (stage == 1) { if (job >= 2 && job < 4) shiftCol = (job - 2) * 320;
                           else if (job == 4) shiftCol = 320; }
    else                 { if (job == 3) shiftCol = 0; }

    __nv_bfloat16 *oh, *ol, *th = nullptr, *tl = nullptr;
    if (stage == 0) {
        if (job < 4) { oh = &g_Uh[1][job][0][0]; ol = &g_Ul[1][job][0][0];
                       th = &g_Th[4 + job][0][0]; tl = &g_Tl[4 + job][0][0]; }
        else         { oh = &g_Ch[1][0][0]; ol = &g_Cl[1][0][0];
                       th = &g_Th[8][0][0]; tl = &g_Tl[8][0][0]; }
    } else if (stage == 1) {
        if (job < 4) { oh = &g_Uh[2][job][0][0]; ol = &g_Ul[2][job][0][0];
                       th = &g_Th[9 + job][0][0]; tl = &g_Tl[9 + job][0][0]; }
        else         { oh = &g_Ch[2][0][0]; ol = &g_Cl[2][0][0]; }
    } else             { oh = &g_Uh[3][job][0][0]; ol = &g_Ul[3][job][0][0]; }

    const int r0 = Mbase + wm * 16 + (lane >> 2);
    const int cb = Nbase + wn * 32 + (lane & 3) * 2;
    #pragma unroll
    for (int ni = 0; ni < 4; ++ni)
        #pragma unroll
        for (int half = 0; half < 2; ++half) {
            const int r = r0 + half * 8;
            const int cc = cb + ni * 8;
            float v0 = acc[ni][half * 2], v1 = acc[ni][half * 2 + 1];
            if (shiftCol >= 0) {
                const float2 sv = *reinterpret_cast<const float2*>(&W[r * 1536 + shiftCol + cc]);
                v0 += sv.x; v1 += sv.y;
            }
            __nv_bfloat16 h0, l0, h1, l1;
            splitbf(v0, h0, l0); splitbf(v1, h1, l1);
            *reinterpret_cast<__nv_bfloat162*>(&oh[r * 256 + cc]) = __nv_bfloat162(h0, h1);
            *reinterpret_cast<__nv_bfloat162*>(&ol[r * 256 + cc]) = __nv_bfloat162(l0, l1);
            if (th) {
                th[cc * 256 + r] = h0; th[(cc + 1) * 256 + r] = h1;
                tl[cc * 256 + r] = l0; tl[(cc + 1) * 256 + r] = l1;
            }
        }
}

// ============================================================================
// phase 1: dense HMMA GEMM  out[65536,256] = X @ Wk^T + bias
// CTA 128x64, 256 thr (8 warps 4Mx2N, warp 32x32), 2-stage, 2 CTA/SM.
// Epilogue: ring seed t=0, split-u for all t>=1.
// ============================================================================
#define P1_STRIDE 144
#define P1_AMAT   18432          // 128*144
#define P1_BMAT   9216           // 64*144
#define P1_STAGE  55296          // Ah|Al|Bh|Bl

__global__ void __launch_bounds__(256) phase1_mma(
    const float* __restrict__ bias, float* __restrict__ out)
{
    extern __shared__ __align__(16) char sm1[];
    const uint32_t sb = smem_u32(sm1);
    const int tid = threadIdx.x, warp = tid >> 5, lane = tid & 31;
    const int Nbase = blockIdx.x * 64;
    const int Mbase = blockIdx.y * 128;
    const int wm = warp >> 1, wn = warp & 1;

    float acc[2][4][4];
    #pragma unroll
    for (int mi = 0; mi < 2; ++mi)
        #pragma unroll
        for (int ni = 0; ni < 4; ++ni)
            #pragma unroll
            for (int q = 0; q < 4; ++q) acc[mi][ni][q] = 0.f;

    auto load = [&](int c, int st) {
        const int k0 = c * 64;
        const uint32_t ab = sb + st * P1_STAGE;
        const char* xh = (const char*)g_Xh + (size_t)Mbase * 1024 + k0 * 2;
        const char* xl = (const char*)g_Xl + (size_t)Mbase * 1024 + k0 * 2;
        const char* kh = (const char*)g_Kh + (size_t)Nbase * 1024 + k0 * 2;
        const char* kl = (const char*)g_Kl + (size_t)Nbase * 1024 + k0 * 2;
        #pragma unroll
        for (int i = 0; i < 4; ++i) {               // A: 128 rows
            const int id = i * 256 + tid;
            const int row = id >> 3, cq = (id & 7) * 16;
            const uint32_t d = ab + row * P1_STRIDE + cq;
            const size_t g = (size_t)row * 1024 + cq;
            cp16(d,           xh + g);
            cp16(d + P1_AMAT, xl + g);
        }
        #pragma unroll
        for (int i = 0; i < 2; ++i) {               // B: 64 rows
            const int id = i * 256 + tid;
            const int row = id >> 3, cq = (id & 7) * 16;
            const uint32_t d = ab + 2 * P1_AMAT + row * P1_STRIDE + cq;
            const size_t g = (size_t)row * 1024 + cq;
            cp16(d,           kh + g);
            cp16(d + P1_BMAT, kl + g);
        }
        cp_commit();
    };

    const uint32_t rsel = (uint32_t)((lane & 15) * P1_STRIDE + (lane >> 4) * 16);

    load(0, 0); load(1, 1);
    for (int c = 0; c < 8; ++c) {
        if (c + 1 < 8) cp_wait<1>(); else cp_wait<0>();
        __syncthreads();
        const uint32_t ab  = sb + (c & 1) * P1_STAGE;
        const uint32_t aA0 = ab + (wm * 32) * P1_STRIDE + rsel;
        const uint32_t aB0 = ab + 2 * P1_AMAT + (wn * 32) * P1_STRIDE + rsel;
        #pragma unroll
        for (int s = 0; s < 4; ++s) {
            const uint32_t off = s * 32;
            uint32_t ah[2][4], al[2][4], bh[2][4], bl[2][4];
            ldx4(ah[0], aA0 + off);
            ldx4(ah[1], aA0 + 16 * P1_STRIDE + off);
            ldx4(al[0], aA0 + P1_AMAT + off);
            ldx4(al[1], aA0 + P1_AMAT + 16 * P1_STRIDE + off);
            ldx4(bh[0], aB0 + off);
            ldx4(bh[1], aB0 + 16 * P1_STRIDE + off);
            ldx4(bl[0], aB0 + P1_BMAT + off);
            ldx4(bl[1], aB0 + P1_BMAT + 16 * P1_STRIDE + off);
            #pragma unroll
            for (int mi = 0; mi < 2; ++mi)
                #pragma unroll
                for (int ni = 0; ni < 4; ++ni) {
                    const int nb = ni >> 1, sel = ni & 1;
                    const uint32_t B0h = bh[nb][sel], B1h = bh[nb][sel + 2];
                    const uint32_t B0l = bl[nb][sel], B1l = bl[nb][sel + 2];
                    mma16816(acc[mi][ni], ah[mi], B0h, B1h);
                    mma16816(acc[mi][ni], al[mi], B0h, B1h);
                    mma16816(acc[mi][ni], ah[mi], B0l, B1l);
                }
        }
        __syncthreads();
        if (c + 2 < 8) load(c + 2, c & 1);
    }

    const int r0 = Mbase + wm * 32 + (lane >> 2);
    const int cb = Nbase + wn * 32 + (lane & 3) * 2;
    #pragma unroll
    for (int mi = 0; mi < 2; ++mi)
        #pragma unroll
        for (int ni = 0; ni < 4; ++ni)
            #pragma unroll
            for (int half = 0; half < 2; ++half) {
                const int r = r0 + mi * 16 + half * 8;
                const int cc = cb + ni * 8;
                const float2 bv = *reinterpret_cast<const float2*>(&bias[cc]);
                const float v0 = acc[mi][ni][half * 2] + bv.x;
                const float v1 = acc[mi][ni][half * 2 + 1] + bv.y;
                *reinterpret_cast<float2*>(&out[(size_t)r * 256 + cc]) = make_float2(v0, v1);
                const int t = (r >> 6) & 63;
                const int rowg = (r >> 12) * 64 + (r & 63);
                __nv_bfloat16 h0, l0, h1, l1;
                splitbf(v0, h0, l0); splitbf(v1, h1, l1);
                if (t == 0) {
                    *reinterpret_cast<__nv_bfloat162*>(&g_zh[0][rowg][cc]) = __nv_bfloat162(h0, h1);
                    *reinterpret_cast<__nv_bfloat162*>(&g_zl[0][rowg][cc]) = __nv_bfloat162(l0, l1);
                } else {
                    *reinterpret_cast<__nv_bfloat162*>(&g_uh[t][rowg][cc]) = __nv_bfloat162(h0, h1);
                    *reinterpret_cast<__nv_bfloat162*>(&g_ul[t][rowg][cc]) = __nv_bfloat162(l0, l1);
                }
            }
}

// ---- vpass: out[t0+d] += sum_{j=1..d} C_j @ u[t0+d-j], blocks t0=4bi+1 ----
__global__ void __launch_bounds__(256) vpass_mma(float* __restrict__ out)
{
    extern __shared__ __align__(16) char smv[];
    const uint32_t sb = smem_u32(smv);
    const int tid = threadIdx.x, warp = tid >> 5, lane = tid & 31;
    const int Nbase = blockIdx.x * 64;
    const int Mbase = blockIdx.y * 64;
    const int bi = blockIdx.z / 3, d = blockIdx.z % 3 + 1;
    const int t0 = 4 * bi + 1, tp = t0 + d;
    if (tp > 63) return;
    const int wm = warp >> 1, wn = warp & 1;
    const int NC = 4 * d;

    float acc[4][4];
    #pragma unroll
    for (int ni = 0; ni < 4; ++ni)
        #pragma unroll
        for (int q = 0; q < 4; ++q) acc[ni][q] = 0.f;

    auto load = [&](int c, int st) {
        const int j = (c >> 2) + 1, k0 = (c & 3) * 64;
        const uint32_t ab = sb + st * P2_BUF;
        const char* sAh = (const char*)&g_uh[tp - j][Mbase][k0];
        const char* sAl = (const char*)&g_ul[tp - j][Mbase][k0];
        const char* sBh = (const char*)&g_Ch[j - 1][Nbase][k0];
        const char* sBl = (const char*)&g_Cl[j - 1][Nbase][k0];
        #pragma unroll
        for (int i = 0; i < 2; ++i) {
            const int id = i * 256 + tid;
            const int row = id >> 3, cq = (id & 7) * 16;
            const uint32_t dd = ab + row * P2_STRIDE + cq;
            const int g = row * 512 + cq;
            cp16(dd,              sAh + g);
            cp16(dd + P2_MAT,     sAl + g);
            cp16(dd + 2 * P2_MAT, sBh + g);
            cp16(dd + 3 * P2_MAT, sBl + g);
        }
        cp_commit();
    };

    const uint32_t rsel = (uint32_t)((lane & 15) * P2_STRIDE + (lane >> 4) * 16);

    load(0, 0); load(1, 1);
    for (int c = 0; c < NC; ++c) {
        if (c + 1 < NC) cp_wait<1>(); else cp_wait<0>();
        __syncthreads();
        const uint32_t ab  = sb + (c & 1) * P2_BUF;
        const uint32_t aA0 = ab + (wm * 16) * P2_STRIDE + rsel;
        const uint32_t aB0 = ab + 2 * P2_MAT + (wn * 32) * P2_STRIDE + rsel;
        #pragma unroll
        for (int s = 0; s < 4; ++s) {
            const uint32_t off = s * 32;
            uint32_t ah[4], al[4], bh[2][4], bl[2][4];
            ldx4(ah, aA0 + off);
            ldx4(al, aA0 + P2_MAT + off);
            ldx4(bh[0], aB0 + off);
            ldx4(bh[1], aB0 + 16 * P2_STRIDE + off);
            ldx4(bl[0], aB0 + P2_MAT + off);
            ldx4(bl[1], aB0 + P2_MAT + 16 * P2_STRIDE + off);
            #pragma unroll
            for (int ni = 0; ni < 4; ++ni) {
                const int nb = ni >> 1, sel = ni & 1;
                mma16816(acc[ni], ah, bh[nb][sel], bh[nb][sel + 2]);
                mma16816(acc[ni], al, bh[nb][sel], bh[nb][sel + 2]);
                mma16816(acc[ni], ah, bl[nb][sel], bl[nb][sel + 2]);
            }
        }
        __syncthreads();
        if (c + 2 < NC) load(c + 2, c & 1);
    }

    const int r0 = Mbase + wm * 16 + (lane >> 2);
    const int cb = Nbase + wn * 32 + (lane & 3) * 2;
    #pragma unroll
    for (int ni = 0; ni < 4; ++ni)
        #pragma unroll
        for (int half = 0; half < 2; ++half) {
            const int r = r0 + half * 8;
            const int cc = cb + ni * 8;
            const int b_ = r >> 6, p_ = r & 63;
            float* op = &out[((b_ * 64 + tp) * 64 + p_) * 256 + cc];
            float2 cur = *reinterpret_cast<float2*>(op);
            cur.x += acc[ni][half * 2];
            cur.y += acc[ni][half * 2 + 1];
            *reinterpret_cast<float2*>(op) = cur;
        }
}

// ---- quad (sequential): d-group computes z_{t0+d} from z_{t0-4..t0-1} ----
__global__ void __launch_bounds__(256) quad_mma(float* __restrict__ out, const int t0)
{
    extern __shared__ __align__(16) char sm2[];
    const uint32_t sb = smem_u32(sm2);
    const int tid = threadIdx.x, warp = tid >> 5, lane = tid & 31;
    const int Nbase = blockIdx.x * 64;
    const int d = blockIdx.y >> 4;
    const int Mbase = (blockIdx.y & 15) * 64;
    const int tOut = t0 + d;
    if (tOut > 63) return;
    const __nv_bfloat16 (*Wh)[256][256] = g_Uh[d];
    const __nv_bfloat16 (*Wl)[256][256] = g_Ul[d];
    const int wm = warp >> 1, wn = warp & 1;

    const int h0 = (t0 >= 4) ? 0 : 4 - t0;
    const int NC = 4 * (4 - h0);

    float acc[4][4];
    #pragma unroll
    for (int ni = 0; ni < 4; ++ni)
        #pragma unroll
        for (int q = 0; q < 4; ++q) acc[ni][q] = 0.f;

    auto load = [&](int c, int st) {
        const int kc = h0 * 4 + c;
        const int h = kc >> 2, ts = t0 - 4 + h, k0 = (kc & 3) * 64;
        const uint32_t ab = sb + st * P2_BUF;
        const char* sAh = (const char*)&g_zh[ts][Mbase][k0];
        const char* sAl = (const char*)&g_zl[ts][Mbase][k0];
        const char* sBh = (const char*)&Wh[h][Nbase][k0];
        const char* sBl = (const char*)&Wl[h][Nbase][k0];
        #pragma unroll
        for (int i = 0; i < 2; ++i) {
            const int id = i * 256 + tid;
            const int row = id >> 3, cq = (id & 7) * 16;
            const uint32_t dd = ab + row * P2_STRIDE + cq;
            const int g = row * 512 + cq;
            cp16(dd,              sAh + g);
            cp16(dd + P2_MAT,     sAl + g);
            cp16(dd + 2 * P2_MAT, sBh + g);
            cp16(dd + 3 * P2_MAT, sBl + g);
        }
        cp_commit();
    };

    const uint32_t rsel = (uint32_t)((lane & 15) * P2_STRIDE + (lane >> 4) * 16);

    load(0, 0); load(1, 1);
    for (int c = 0; c < NC; ++c) {
        if (c + 1 < NC) cp_wait<1>(); else cp_wait<0>();
        __syncthreads();
        const uint32_t ab  = sb + (c & 1) * P2_BUF;
        const uint32_t aA0 = ab + (wm * 16) * P2_STRIDE + rsel;
        const uint32_t aB0 = ab + 2 * P2_MAT + (wn * 32) * P2_STRIDE + rsel;
        #pragma unroll
        for (int s = 0; s < 4; ++s) {
            const uint32_t off = s * 32;
            uint32_t ah[4], al[4], bh[2][4], bl[2][4];
            ldx4(ah, aA0 + off);
            ldx4(al, aA0 + P2_MAT + off);
            ldx4(bh[0], aB0 + off);
            ldx4(bh[1], aB0 + 16 * P2_STRIDE + off);
            ldx4(bl[0], aB0 + P2_MAT + off);
            ldx4(bl[1], aB0 + P2_MAT + 16 * P2_STRIDE + off);
            #pragma unroll
            for (int ni = 0; ni < 4; ++ni) {
                const int nb = ni >> 1, sel = ni & 1;
                mma16816(acc[ni], ah, bh[nb][sel], bh[nb][sel + 2]);
                mma16816(acc[ni], al, bh[nb][sel], bh[nb][sel + 2]);
                mma16816(acc[ni], ah, bl[nb][sel], bl[nb][sel + 2]);
            }
        }
        __syncthreads();
        if (c + 2 < NC) load(c + 2, c & 1);
    }

    const int r0 = Mbase + wm * 16 + (lane >> 2);
    const int cb = Nbase + wn * 32 + (lane & 3) * 2;
    #pragma unroll
    for (int ni = 0; ni < 4; ++ni)
        #pragma unroll
        for (int half = 0; half < 2; ++half) {
            const int r = r0 + half * 8;
            const int cc = cb + ni * 8;
            const int b_ = r >> 6, p_ = r & 63;
            float* op = &out[((b_ * 64 + tOut) * 64 + p_) * 256 + cc];
            float2 cur = *reinterpret_cast<float2*>(op);
            const float v0 = cur.x + acc[ni][half * 2];
            const float v1 = cur.y + acc[ni][half * 2 + 1];
            *reinterpret_cast<float2*>(op) = make_float2(v0, v1);
            __nv_bfloat16 h0, l0, h1, l1;
            splitbf(v0, h0, l0); splitbf(v1, h1, l1);
            *reinterpret_cast<__nv_bfloat162*>(&g_zh[tOut][r][cc]) = __nv_bfloat162(h0, h1);
            *reinterpret_cast<__nv_bfloat162*>(&g_zl[tOut][r][cc]) = __nv_bfloat162(l0, l1);
        }
}

// ---------- launch ----------
extern "C" void kernel_launch(void* const* d_in, const int* in_sizes, int n_in,
                              void* d_out, int out_size)
{
    const float* o_in = (const float*)d_in[0];   // (16,64,64,256)
    const float* a_in = (const float*)d_in[1];   // (16,64,64,64)
    const float* W_in = (const float*)d_in[2];   // (256,1536)
    const float* b_in = (const float*)d_in[3];   // (256,)
    float* out = (float*)d_out;                  // (16,64,64,256)

    cudaFuncSetAttribute(phase1_mma, cudaFuncAttributeMaxDynamicSharedMemorySize, 2 * P1_STAGE);
    cudaFuncSetAttribute(prepG_mma, cudaFuncAttributeMaxDynamicSharedMemorySize, 2 * P2_BUF);
    cudaFuncSetAttribute(vpass_mma, cudaFuncAttributeMaxDynamicSharedMemorySize, 2 * P2_BUF);
    cudaFuncSetAttribute(quad_mma, cudaFuncAttributeMaxDynamicSharedMemorySize, 2 * P2_BUF);

    prepW_kernel<<<1536, 256>>>(W_in);
    prepX_kernel<<<32768, 256>>>(o_in, a_in);
    prepG_mma<<<dim3(4, 4, 5), 256, 2 * P2_BUF>>>(W_in, 0);
    prepG_mma<<<dim3(4, 4, 5), 256, 2 * P2_BUF>>>(W_in, 1);
    prepG_mma<<<dim3(4, 4, 4), 256, 2 * P2_BUF>>>(W_in, 2);
    phase1_mma<<<dim3(4, 512), 256, 2 * P1_STAGE>>>(b_in, out);
    vpass_mma<<<dim3(4, 16, 48), 256, 2 * P2_BUF>>>(out);
    for (int bi = 0; bi < 16; ++bi)              // 16 sequential 4-step blocks
        quad_mma<<<dim3(4, 64), 256, 2 * P2_BUF>>>(out, 1 + 4 * bi);
}